// round 3
// baseline (speedup 1.0000x reference)
#include <cuda_runtime.h>
#include <cstdint>

// Problem: B=4096, D=128, H=512
//   z = y @ W1 + t*v1 + b1 ; h = tanh(z) ; dy = h @ W2 + b2
//   div[b] = sum_k (1 - h[b,k]^2) * c_k,  c_k = sum_i W1[i,k]*W2[k,i]
// Output: dy (B*D floats) followed by -div (B floats).
// GEMMs via mma.sync m16n8k8 tf32 with 3xTF32 split (fp32-grade accuracy).

#define B_ 4096
#define D_ 128
#define H_ 512
#define BM 16
#define SP 132   // padded smem row stride (conflict-free A-frag reads)

__device__ float g_c[H_];     // c_k
__device__ float g_tb[H_];    // t*v1 + b1
// Weights pre-split (hi/lo tf32) and pre-packed in mma B-fragment order:
// element W[k][n] -> dst = ((kt*NT + nt)*32 + gid*4 + tig)*2 + reg
//   kt=k>>3, tig=k&3, reg=(k>>2)&1, nt=n>>3, gid=n&7
__device__ float g_W1p_hi[D_ * H_];
__device__ float g_W1p_lo[D_ * H_];
__device__ float g_W2p_hi[H_ * D_];
__device__ float g_W2p_lo[H_ * D_];

__device__ __forceinline__ float to_tf32(float x) {
    float r; asm("cvt.rna.tf32.f32 %0, %1;" : "=f"(r) : "f"(x)); return r;
}

__device__ __forceinline__ void mma_tf32(float c[4],
                                         uint32_t a0, uint32_t a1, uint32_t a2, uint32_t a3,
                                         uint32_t b0, uint32_t b1) {
    asm volatile(
        "mma.sync.aligned.m16n8k8.row.col.f32.tf32.tf32.f32 "
        "{%0,%1,%2,%3}, {%4,%5,%6,%7}, {%8,%9}, {%0,%1,%2,%3};\n"
        : "+f"(c[0]), "+f"(c[1]), "+f"(c[2]), "+f"(c[3])
        : "r"(a0), "r"(a1), "r"(a2), "r"(a3), "r"(b0), "r"(b1));
}

__global__ void prep_kernel(const float* __restrict__ t,
                            const float* __restrict__ W1,
                            const float* __restrict__ b1,
                            const float* __restrict__ v1,
                            const float* __restrict__ W2) {
    int k = blockIdx.x * blockDim.x + threadIdx.x;
    if (k < H_) {
        float s = 0.f;
        #pragma unroll 8
        for (int i = 0; i < D_; i++) s += W1[i * H_ + k] * W2[k * D_ + i];
        g_c[k]  = s;
        g_tb[k] = b1[k] + t[0] * v1[k];
    }
}

__global__ void pack_kernel(const float* __restrict__ W1,
                            const float* __restrict__ W2) {
    int idx = blockIdx.x * blockDim.x + threadIdx.x;
    if (idx < D_ * H_) {
        int k = idx >> 9, n = idx & (H_ - 1);
        float w  = W1[idx];
        float hi = to_tf32(w), lo = to_tf32(w - hi);
        int kt = k >> 3, tig = k & 3, reg = (k >> 2) & 1, nt = n >> 3, gid = n & 7;
        int dst = ((kt * (H_ / 8) + nt) * 32 + gid * 4 + tig) * 2 + reg;
        g_W1p_hi[dst] = hi; g_W1p_lo[dst] = lo;
    } else if (idx < 2 * D_ * H_) {
        int i2 = idx - D_ * H_;
        int k = i2 >> 7, n = i2 & (D_ - 1);
        float w  = W2[i2];
        float hi = to_tf32(w), lo = to_tf32(w - hi);
        int kt = k >> 3, tig = k & 3, reg = (k >> 2) & 1, nt = n >> 3, gid = n & 7;
        int dst = ((kt * (D_ / 8) + nt) * 32 + gid * 4 + tig) * 2 + reg;
        g_W2p_hi[dst] = hi; g_W2p_lo[dst] = lo;
    }
}

__global__ __launch_bounds__(256, 2) void ode_kernel(
    const float* __restrict__ y,
    const float* __restrict__ b2,
    float* __restrict__ out)
{
    __shared__ float yh[BM][SP], yl[BM][SP];
    __shared__ float hh[BM][SP], hl[BM][SP];
    __shared__ float sdv[BM][8];

    const int tid  = threadIdx.x;
    const int warp = tid >> 5;      // 0..7
    const int lane = tid & 31;
    const int gid  = lane >> 2;     // 0..7
    const int tig  = lane & 3;      // 0..3
    const int mb   = blockIdx.x * BM;

    // Load + split y tile (16 x 128)
    for (int i = tid; i < BM * (D_ / 4); i += 256) {
        int r = i >> 5, c4 = (i & 31) * 4;
        float4 v = *(const float4*)(y + (size_t)(mb + r) * D_ + c4);
        float x;
        x = to_tf32(v.x); yh[r][c4]     = x; yl[r][c4]     = to_tf32(v.x - x);
        x = to_tf32(v.y); yh[r][c4 + 1] = x; yl[r][c4 + 1] = to_tf32(v.y - x);
        x = to_tf32(v.z); yh[r][c4 + 2] = x; yl[r][c4 + 2] = to_tf32(v.z - x);
        x = to_tf32(v.w); yh[r][c4 + 3] = x; yl[r][c4 + 3] = to_tf32(v.w - x);
    }
    __syncthreads();

    float acc[2][4] = {};        // dy frags: 2 n-tiles of 8 cols (warp covers 16 cols)
    float dv0 = 0.f, dv1 = 0.f;  // divergence partials, rows gid and gid+8

    for (int ch = 0; ch < H_ / 128; ch++) {
        // ---- Phase A: z = y_tile @ W1[:, ch*128 .. +128]; warp covers 16 cols ----
        float z[2][4] = {};
        #pragma unroll 4
        for (int kt = 0; kt < 16; kt++) {
            int kc = kt * 8 + tig;
            uint32_t ah0 = __float_as_uint(yh[gid][kc]);
            uint32_t ah1 = __float_as_uint(yh[gid + 8][kc]);
            uint32_t ah2 = __float_as_uint(yh[gid][kc + 4]);
            uint32_t ah3 = __float_as_uint(yh[gid + 8][kc + 4]);
            uint32_t al0 = __float_as_uint(yl[gid][kc]);
            uint32_t al1 = __float_as_uint(yl[gid + 8][kc]);
            uint32_t al2 = __float_as_uint(yl[gid][kc + 4]);
            uint32_t al3 = __float_as_uint(yl[gid + 8][kc + 4]);
            #pragma unroll
            for (int nt = 0; nt < 2; nt++) {
                int ntg = ch * 16 + warp * 2 + nt;
                uint2 bh = ((const uint2*)g_W1p_hi)[(kt * (H_ / 8) + ntg) * 32 + lane];
                uint2 bl = ((const uint2*)g_W1p_lo)[(kt * (H_ / 8) + ntg) * 32 + lane];
                mma_tf32(z[nt], ah0, ah1, ah2, ah3, bh.x, bh.y);
                mma_tf32(z[nt], ah0, ah1, ah2, ah3, bl.x, bl.y);
                mma_tf32(z[nt], al0, al1, al2, al3, bh.x, bh.y);
            }
        }

        // ---- tanh + divergence + split h into smem ----
        #pragma unroll
        for (int nt = 0; nt < 2; nt++) {
            int lc   = warp * 16 + nt * 8 + tig * 2;  // col within chunk [0,128)
            int gc   = ch * 128 + lc;                 // global H col
            float tb0 = g_tb[gc],  tb1 = g_tb[gc + 1];
            float cc0 = g_c[gc],   cc1 = g_c[gc + 1];
            float h00 = tanhf(z[nt][0] + tb0);
            float h01 = tanhf(z[nt][1] + tb1);
            float h10 = tanhf(z[nt][2] + tb0);
            float h11 = tanhf(z[nt][3] + tb1);
            dv0 += cc0 * (1.f - h00 * h00) + cc1 * (1.f - h01 * h01);
            dv1 += cc0 * (1.f - h10 * h10) + cc1 * (1.f - h11 * h11);
            float x;
            x = to_tf32(h00); hh[gid][lc]         = x; hl[gid][lc]         = to_tf32(h00 - x);
            x = to_tf32(h01); hh[gid][lc + 1]     = x; hl[gid][lc + 1]     = to_tf32(h01 - x);
            x = to_tf32(h10); hh[gid + 8][lc]     = x; hl[gid + 8][lc]     = to_tf32(h10 - x);
            x = to_tf32(h11); hh[gid + 8][lc + 1] = x; hl[gid + 8][lc + 1] = to_tf32(h11 - x);
        }
        __syncthreads();

        // ---- Phase B: acc += h_chunk @ W2[ch*128 .. , :]; warp covers 16 D-cols ----
        #pragma unroll 4
        for (int kt = 0; kt < 16; kt++) {
            int kc = kt * 8 + tig;
            uint32_t ah0 = __float_as_uint(hh[gid][kc]);
            uint32_t ah1 = __float_as_uint(hh[gid + 8][kc]);
            uint32_t ah2 = __float_as_uint(hh[gid][kc + 4]);
            uint32_t ah3 = __float_as_uint(hh[gid + 8][kc + 4]);
            uint32_t al0 = __float_as_uint(hl[gid][kc]);
            uint32_t al1 = __float_as_uint(hl[gid + 8][kc]);
            uint32_t al2 = __float_as_uint(hl[gid][kc + 4]);
            uint32_t al3 = __float_as_uint(hl[gid + 8][kc + 4]);
            int ktg = ch * 16 + kt;
            #pragma unroll
            for (int nt = 0; nt < 2; nt++) {
                int ntg = warp * 2 + nt;
                uint2 bh = ((const uint2*)g_W2p_hi)[(ktg * (D_ / 8) + ntg) * 32 + lane];
                uint2 bl = ((const uint2*)g_W2p_lo)[(ktg * (D_ / 8) + ntg) * 32 + lane];
                mma_tf32(acc[nt], ah0, ah1, ah2, ah3, bh.x, bh.y);
                mma_tf32(acc[nt], ah0, ah1, ah2, ah3, bl.x, bl.y);
                mma_tf32(acc[nt], al0, al1, al2, al3, bh.x, bh.y);
            }
        }
        __syncthreads();   // protect hh/hl before next chunk overwrites
    }

    // ---- Epilogue: dy = acc + b2 ----
    #pragma unroll
    for (int nt = 0; nt < 2; nt++) {
        int col = warp * 16 + nt * 8 + tig * 2;
        float b20 = b2[col], b21 = b2[col + 1];
        float2 o0 = make_float2(acc[nt][0] + b20, acc[nt][1] + b21);
        float2 o1 = make_float2(acc[nt][2] + b20, acc[nt][3] + b21);
        *(float2*)(out + (size_t)(mb + gid) * D_ + col)     = o0;
        *(float2*)(out + (size_t)(mb + gid + 8) * D_ + col) = o1;
    }

    // ---- Divergence reduce: sum over tig (4 lanes), then across 8 warps ----
    dv0 += __shfl_xor_sync(0xFFFFFFFFu, dv0, 1);
    dv0 += __shfl_xor_sync(0xFFFFFFFFu, dv0, 2);
    dv1 += __shfl_xor_sync(0xFFFFFFFFu, dv1, 1);
    dv1 += __shfl_xor_sync(0xFFFFFFFFu, dv1, 2);
    if (tig == 0) {
        sdv[gid][warp]     = dv0;
        sdv[gid + 8][warp] = dv1;
    }
    __syncthreads();
    if (tid < BM) {
        float s = 0.f;
        #pragma unroll
        for (int w = 0; w < 8; w++) s += sdv[tid][w];
        out[(size_t)B_ * D_ + mb + tid] = -s;
    }
}

extern "C" void kernel_launch(void* const* d_in, const int* in_sizes, int n_in,
                              void* d_out, int out_size) {
    // Input order: t, y, logp, W1, b1, v1, W2, b2
    const float* t  = (const float*)d_in[0];
    const float* y  = (const float*)d_in[1];
    const float* W1 = (const float*)d_in[3];
    const float* b1 = (const float*)d_in[4];
    const float* v1 = (const float*)d_in[5];
    const float* W2 = (const float*)d_in[6];
    const float* b2 = (const float*)d_in[7];
    float* out = (float*)d_out;

    prep_kernel<<<1, H_>>>(t, W1, b1, v1, W2);
    pack_kernel<<<(2 * D_ * H_) / 256, 256>>>(W1, W2);
    ode_kernel<<<B_ / BM, 256>>>(y, b2, out);
}

// round 4
// speedup vs baseline: 1.9857x; 1.9857x over previous
#include <cuda_runtime.h>
#include <cstdint>

// Problem: B=4096, D=128, H=512
//   z = y @ W1 + t*v1 + b1 ; h = tanh(z) ; dy = h @ W2 + b2
//   div[b] = sum_k (1 - h[b,k]^2) * c_k,  c_k = sum_i W1[i,k]*W2[k,i]
// Output: dy (B*D floats) followed by -div (B floats).
// GEMMs via mma.sync m16n8k8 tf32 with 3xTF32 split (fp32-grade accuracy).

#define B_ 4096
#define D_ 128
#define H_ 512
#define BM 16
#define SP 132   // padded smem row stride (conflict-free A-frag reads)

__device__ float g_c[H_];     // c_k
__device__ float g_tb[H_];    // t*v1 + b1
// Weights pre-split (hi/lo tf32) and pre-packed in mma B-fragment order:
// element W[k][n] -> dst = ((kt*NT + nt)*32 + gid*4 + tig)*2 + reg
//   kt=k>>3, tig=k&3, reg=(k>>2)&1, nt=n>>3, gid=n&7
__device__ float g_W1p_hi[D_ * H_];
__device__ float g_W1p_lo[D_ * H_];
__device__ float g_W2p_hi[H_ * D_];
__device__ float g_W2p_lo[H_ * D_];

__device__ __forceinline__ float to_tf32(float x) {
    float r; asm("cvt.rna.tf32.f32 %0, %1;" : "=f"(r) : "f"(x)); return r;
}

__device__ __forceinline__ void mma_tf32(float c[4],
                                         uint32_t a0, uint32_t a1, uint32_t a2, uint32_t a3,
                                         uint32_t b0, uint32_t b1) {
    asm volatile(
        "mma.sync.aligned.m16n8k8.row.col.f32.tf32.tf32.f32 "
        "{%0,%1,%2,%3}, {%4,%5,%6,%7}, {%8,%9}, {%0,%1,%2,%3};\n"
        : "+f"(c[0]), "+f"(c[1]), "+f"(c[2]), "+f"(c[3])
        : "r"(a0), "r"(a1), "r"(a2), "r"(a3), "r"(b0), "r"(b1));
}

// One warp per H-column k: lane-strided partial dot of W1[:,k].W2[k,:] + shuffle reduce.
__global__ __launch_bounds__(256) void prep_kernel(
    const float* __restrict__ t,
    const float* __restrict__ W1,
    const float* __restrict__ b1,
    const float* __restrict__ v1,
    const float* __restrict__ W2) {
    const int warp = (blockIdx.x * blockDim.x + threadIdx.x) >> 5;  // 0..511 = k
    const int lane = threadIdx.x & 31;
    const int k = warp;
    float s = 0.f;
    #pragma unroll
    for (int i = lane; i < D_; i += 32)
        s += W1[(size_t)i * H_ + k] * W2[(size_t)k * D_ + i];
    #pragma unroll
    for (int off = 16; off > 0; off >>= 1)
        s += __shfl_xor_sync(0xFFFFFFFFu, s, off);
    if (lane == 0) {
        g_c[k]  = s;
        g_tb[k] = b1[k] + t[0] * v1[k];
    }
}

__global__ __launch_bounds__(256) void pack_kernel(
    const float* __restrict__ W1,
    const float* __restrict__ W2) {
    int idx = blockIdx.x * blockDim.x + threadIdx.x;
    if (idx < D_ * H_) {
        int k = idx >> 9, n = idx & (H_ - 1);
        float w  = W1[idx];
        float hi = to_tf32(w), lo = to_tf32(w - hi);
        int kt = k >> 3, tig = k & 3, reg = (k >> 2) & 1, nt = n >> 3, gid = n & 7;
        int dst = ((kt * (H_ / 8) + nt) * 32 + gid * 4 + tig) * 2 + reg;
        g_W1p_hi[dst] = hi; g_W1p_lo[dst] = lo;
    } else if (idx < 2 * D_ * H_) {
        int i2 = idx - D_ * H_;
        int k = i2 >> 7, n = i2 & (D_ - 1);
        float w  = W2[i2];
        float hi = to_tf32(w), lo = to_tf32(w - hi);
        int kt = k >> 3, tig = k & 3, reg = (k >> 2) & 1, nt = n >> 3, gid = n & 7;
        int dst = ((kt * (D_ / 8) + nt) * 32 + gid * 4 + tig) * 2 + reg;
        g_W2p_hi[dst] = hi; g_W2p_lo[dst] = lo;
    }
}

__global__ __launch_bounds__(256, 2) void ode_kernel(
    const float* __restrict__ y,
    const float* __restrict__ b2,
    float* __restrict__ out)
{
    __shared__ float yh[BM][SP], yl[BM][SP];
    __shared__ float hh[BM][SP], hl[BM][SP];
    __shared__ float sdv[BM][8];

    const int tid  = threadIdx.x;
    const int warp = tid >> 5;      // 0..7
    const int lane = tid & 31;
    const int gid  = lane >> 2;     // 0..7
    const int tig  = lane & 3;      // 0..3
    const int mb   = blockIdx.x * BM;

    // Load + split y tile (16 x 128)
    for (int i = tid; i < BM * (D_ / 4); i += 256) {
        int r = i >> 5, c4 = (i & 31) * 4;
        float4 v = *(const float4*)(y + (size_t)(mb + r) * D_ + c4);
        float x;
        x = to_tf32(v.x); yh[r][c4]     = x; yl[r][c4]     = to_tf32(v.x - x);
        x = to_tf32(v.y); yh[r][c4 + 1] = x; yl[r][c4 + 1] = to_tf32(v.y - x);
        x = to_tf32(v.z); yh[r][c4 + 2] = x; yl[r][c4 + 2] = to_tf32(v.z - x);
        x = to_tf32(v.w); yh[r][c4 + 3] = x; yl[r][c4 + 3] = to_tf32(v.w - x);
    }
    __syncthreads();

    float acc[2][4] = {};        // dy frags: 2 n-tiles of 8 cols (warp covers 16 cols)
    float dv0 = 0.f, dv1 = 0.f;  // divergence partials, rows gid and gid+8

    for (int ch = 0; ch < H_ / 128; ch++) {
        // ---- Phase A: z = y_tile @ W1[:, ch*128 .. +128]; warp covers 16 cols ----
        float z[2][4] = {};
        #pragma unroll 4
        for (int kt = 0; kt < 16; kt++) {
            int kc = kt * 8 + tig;
            uint32_t ah0 = __float_as_uint(yh[gid][kc]);
            uint32_t ah1 = __float_as_uint(yh[gid + 8][kc]);
            uint32_t ah2 = __float_as_uint(yh[gid][kc + 4]);
            uint32_t ah3 = __float_as_uint(yh[gid + 8][kc + 4]);
            uint32_t al0 = __float_as_uint(yl[gid][kc]);
            uint32_t al1 = __float_as_uint(yl[gid + 8][kc]);
            uint32_t al2 = __float_as_uint(yl[gid][kc + 4]);
            uint32_t al3 = __float_as_uint(yl[gid + 8][kc + 4]);
            #pragma unroll
            for (int nt = 0; nt < 2; nt++) {
                int ntg = ch * 16 + warp * 2 + nt;
                uint2 bh = ((const uint2*)g_W1p_hi)[(kt * (H_ / 8) + ntg) * 32 + lane];
                uint2 bl = ((const uint2*)g_W1p_lo)[(kt * (H_ / 8) + ntg) * 32 + lane];
                mma_tf32(z[nt], ah0, ah1, ah2, ah3, bh.x, bh.y);
                mma_tf32(z[nt], ah0, ah1, ah2, ah3, bl.x, bl.y);
                mma_tf32(z[nt], al0, al1, al2, al3, bh.x, bh.y);
            }
        }

        // ---- tanh + divergence + split h into smem ----
        #pragma unroll
        for (int nt = 0; nt < 2; nt++) {
            int lc   = warp * 16 + nt * 8 + tig * 2;  // col within chunk [0,128)
            int gc   = ch * 128 + lc;                 // global H col
            float tb0 = g_tb[gc],  tb1 = g_tb[gc + 1];
            float cc0 = g_c[gc],   cc1 = g_c[gc + 1];
            float h00 = tanhf(z[nt][0] + tb0);
            float h01 = tanhf(z[nt][1] + tb1);
            float h10 = tanhf(z[nt][2] + tb0);
            float h11 = tanhf(z[nt][3] + tb1);
            dv0 += cc0 * (1.f - h00 * h00) + cc1 * (1.f - h01 * h01);
            dv1 += cc0 * (1.f - h10 * h10) + cc1 * (1.f - h11 * h11);
            float x;
            x = to_tf32(h00); hh[gid][lc]         = x; hl[gid][lc]         = to_tf32(h00 - x);
            x = to_tf32(h01); hh[gid][lc + 1]     = x; hl[gid][lc + 1]     = to_tf32(h01 - x);
            x = to_tf32(h10); hh[gid + 8][lc]     = x; hl[gid + 8][lc]     = to_tf32(h10 - x);
            x = to_tf32(h11); hh[gid + 8][lc + 1] = x; hl[gid + 8][lc + 1] = to_tf32(h11 - x);
        }
        __syncthreads();

        // ---- Phase B: acc += h_chunk @ W2[ch*128 .. , :]; warp covers 16 D-cols ----
        #pragma unroll 4
        for (int kt = 0; kt < 16; kt++) {
            int kc = kt * 8 + tig;
            uint32_t ah0 = __float_as_uint(hh[gid][kc]);
            uint32_t ah1 = __float_as_uint(hh[gid + 8][kc]);
            uint32_t ah2 = __float_as_uint(hh[gid][kc + 4]);
            uint32_t ah3 = __float_as_uint(hh[gid + 8][kc + 4]);
            uint32_t al0 = __float_as_uint(hl[gid][kc]);
            uint32_t al1 = __float_as_uint(hl[gid + 8][kc]);
            uint32_t al2 = __float_as_uint(hl[gid][kc + 4]);
            uint32_t al3 = __float_as_uint(hl[gid + 8][kc + 4]);
            int ktg = ch * 16 + kt;
            #pragma unroll
            for (int nt = 0; nt < 2; nt++) {
                int ntg = warp * 2 + nt;
                uint2 bh = ((const uint2*)g_W2p_hi)[(ktg * (D_ / 8) + ntg) * 32 + lane];
                uint2 bl = ((const uint2*)g_W2p_lo)[(ktg * (D_ / 8) + ntg) * 32 + lane];
                mma_tf32(acc[nt], ah0, ah1, ah2, ah3, bh.x, bh.y);
                mma_tf32(acc[nt], ah0, ah1, ah2, ah3, bl.x, bl.y);
                mma_tf32(acc[nt], al0, al1, al2, al3, bh.x, bh.y);
            }
        }
        __syncthreads();   // protect hh/hl before next chunk overwrites
    }

    // ---- Epilogue: dy = acc + b2 ----
    #pragma unroll
    for (int nt = 0; nt < 2; nt++) {
        int col = warp * 16 + nt * 8 + tig * 2;
        float b20 = b2[col], b21 = b2[col + 1];
        float2 o0 = make_float2(acc[nt][0] + b20, acc[nt][1] + b21);
        float2 o1 = make_float2(acc[nt][2] + b20, acc[nt][3] + b21);
        *(float2*)(out + (size_t)(mb + gid) * D_ + col)     = o0;
        *(float2*)(out + (size_t)(mb + gid + 8) * D_ + col) = o1;
    }

    // ---- Divergence reduce: sum over tig (4 lanes), then across 8 warps ----
    dv0 += __shfl_xor_sync(0xFFFFFFFFu, dv0, 1);
    dv0 += __shfl_xor_sync(0xFFFFFFFFu, dv0, 2);
    dv1 += __shfl_xor_sync(0xFFFFFFFFu, dv1, 1);
    dv1 += __shfl_xor_sync(0xFFFFFFFFu, dv1, 2);
    if (tig == 0) {
        sdv[gid][warp]     = dv0;
        sdv[gid + 8][warp] = dv1;
    }
    __syncthreads();
    if (tid < BM) {
        float s = 0.f;
        #pragma unroll
        for (int w = 0; w < 8; w++) s += sdv[tid][w];
        out[(size_t)B_ * D_ + mb + tid] = -s;
    }
}

extern "C" void kernel_launch(void* const* d_in, const int* in_sizes, int n_in,
                              void* d_out, int out_size) {
    // Input order: t, y, logp, W1, b1, v1, W2, b2
    const float* t  = (const float*)d_in[0];
    const float* y  = (const float*)d_in[1];
    const float* W1 = (const float*)d_in[3];
    const float* b1 = (const float*)d_in[4];
    const float* v1 = (const float*)d_in[5];
    const float* W2 = (const float*)d_in[6];
    const float* b2 = (const float*)d_in[7];
    float* out = (float*)d_out;

    prep_kernel<<<(H_ * 32) / 256, 256>>>(t, W1, b1, v1, W2);   // 64 blocks, warp per k
    pack_kernel<<<(2 * D_ * H_) / 256, 256>>>(W1, W2);
    ode_kernel<<<B_ / BM, 256>>>(y, b2, out);
}

// round 5
// speedup vs baseline: 4.4202x; 2.2261x over previous
#include <cuda_runtime.h>
#include <cuda_bf16.h>
#include <cstdint>

// Problem: B=4096, D=128, H=512
//   z = y @ W1 + t*v1 + b1 ; h = tanh(z) ; dy = h @ W2 + b2
//   div[b] = sum_k (1 - h[b,k]^2) * c_k,  c_k = sum_i W1[i,k]*W2[k,i]
// Output: dy (B*D floats) then -div (B floats).
// GEMMs: mma.sync m16n8k16 bf16 with 3-term bf16 split (ahi*bhi + ahi*blo + alo*bhi),
// fp32 accumulate. A-frags via ldmatrix from smem; B-frags prepacked uint4 {hi,hi,lo,lo}.

#define B_ 4096
#define D_ 128
#define H_ 512
#define BM 16
#define SU 68   // smem row stride in uint32 (272B): ldmatrix conflict-free, STS conflict-free

__device__ float g_c[H_];
__device__ float g_tb[H_];
// W1 frags: kt in [0,8) (D/16), nt in [0,64) (H/8). W2: kt in [0,32), nt in [0,16).
// Per (kt,nt): 32 lanes x uint4 {bhi_k0..7, bhi_k8..15, blo_k0..7, blo_k8..15}
__device__ uint4 g_W1p[512 * 32];
__device__ uint4 g_W2p[512 * 32];

__device__ __forceinline__ void split2(float a, float b, uint32_t& hi, uint32_t& lo) {
    __nv_bfloat16 ah = __float2bfloat16_rn(a);
    __nv_bfloat16 bh = __float2bfloat16_rn(b);
    __nv_bfloat16 al = __float2bfloat16_rn(a - __bfloat162float(ah));
    __nv_bfloat16 bl = __float2bfloat16_rn(b - __bfloat162float(bh));
    __nv_bfloat162 hp = __halves2bfloat162(ah, bh);
    __nv_bfloat162 lp = __halves2bfloat162(al, bl);
    hi = *reinterpret_cast<uint32_t*>(&hp);
    lo = *reinterpret_cast<uint32_t*>(&lp);
}

__device__ __forceinline__ void mma_bf16(float c[4], const uint32_t a[4],
                                         uint32_t b0, uint32_t b1) {
    asm volatile(
        "mma.sync.aligned.m16n8k16.row.col.f32.bf16.bf16.f32 "
        "{%0,%1,%2,%3}, {%4,%5,%6,%7}, {%8,%9}, {%0,%1,%2,%3};\n"
        : "+f"(c[0]), "+f"(c[1]), "+f"(c[2]), "+f"(c[3])
        : "r"(a[0]), "r"(a[1]), "r"(a[2]), "r"(a[3]), "r"(b0), "r"(b1));
}

__device__ __forceinline__ void ldsm4(uint32_t r[4], uint32_t addr) {
    asm volatile("ldmatrix.sync.aligned.m8n8.x4.shared.b16 {%0,%1,%2,%3}, [%4];"
                 : "=r"(r[0]), "=r"(r[1]), "=r"(r[2]), "=r"(r[3]) : "r"(addr));
}

// 16 blocks x 256 thr; block handles 32 H-columns; W1 column reads via smem transpose.
__global__ __launch_bounds__(256) void prep_kernel(
    const float* __restrict__ t,  const float* __restrict__ W1,
    const float* __restrict__ b1, const float* __restrict__ v1,
    const float* __restrict__ W2) {
    __shared__ float W1t[128][33];
    const int tid = threadIdx.x;
    const int kbase = blockIdx.x * 32;
    for (int i = tid; i < 128 * 32; i += 256) {
        int r = i >> 5, kk = i & 31;
        W1t[r][kk] = W1[(size_t)r * H_ + kbase + kk];
    }
    __syncthreads();
    const int kk = tid >> 3, sub = tid & 7;
    float s = 0.f;
    #pragma unroll 4
    for (int i = sub; i < 128; i += 8)
        s += W1t[i][kk] * W2[(size_t)(kbase + kk) * D_ + i];
    s += __shfl_xor_sync(0xFFFFFFFFu, s, 1);
    s += __shfl_xor_sync(0xFFFFFFFFu, s, 2);
    s += __shfl_xor_sync(0xFFFFFFFFu, s, 4);
    if (sub == 0) {
        int k = kbase + kk;
        g_c[k]  = s;
        g_tb[k] = b1[k] + t[0] * v1[k];
    }
}

// 512 blocks x 256: one thread per packed uint32 component.
__global__ __launch_bounds__(256) void pack_kernel(
    const float* __restrict__ W1, const float* __restrict__ W2) {
    int idx  = blockIdx.x * 256 + threadIdx.x;   // 0..131071
    int comp = idx & 3;
    int lane = (idx >> 2) & 31;
    int frag = idx >> 7;
    int tig = lane & 3, gid = lane >> 2;
    int reg = comp & 1;
    bool ishi = comp < 2;
    float a, b;
    if (frag < 512) {  // W1: kt<8, nt<64
        int kt = frag >> 6, nt = frag & 63;
        int k0 = kt * 16 + 2 * tig + reg * 8;
        int n  = nt * 8 + gid;
        a = W1[(size_t)k0 * H_ + n];
        b = W1[(size_t)(k0 + 1) * H_ + n];
        uint32_t hi, lo; split2(a, b, hi, lo);
        ((uint32_t*)g_W1p)[frag * 128 + lane * 4 + comp] = ishi ? hi : lo;
    } else {           // W2: kt<32, nt<16
        int f2 = frag - 512;
        int kt = f2 >> 4, nt = f2 & 15;
        int k0 = kt * 16 + 2 * tig + reg * 8;
        int n  = nt * 8 + gid;
        a = W2[(size_t)k0 * D_ + n];
        b = W2[(size_t)(k0 + 1) * D_ + n];
        uint32_t hi, lo; split2(a, b, hi, lo);
        ((uint32_t*)g_W2p)[f2 * 128 + lane * 4 + comp] = ishi ? hi : lo;
    }
}

__global__ __launch_bounds__(256, 2) void ode_kernel(
    const float* __restrict__ y,
    const float* __restrict__ b2,
    float* __restrict__ out)
{
    __shared__ __align__(16) uint32_t yh[BM * SU], yl[BM * SU];
    __shared__ __align__(16) uint32_t hh[BM * SU], hl[BM * SU];
    __shared__ float sdv[BM][8];

    const int tid  = threadIdx.x;
    const int warp = tid >> 5;
    const int lane = tid & 31;
    const int gid  = lane >> 2;
    const int tig  = lane & 3;
    const int mb   = blockIdx.x * BM;

    // Load + bf16-split y tile (16 x 128)
    for (int i = tid; i < BM * 32; i += 256) {
        int r = i >> 5, c4 = (i & 31) * 4;
        float4 v = *(const float4*)(y + (size_t)(mb + r) * D_ + c4);
        uint32_t h0, l0, h1, l1;
        split2(v.x, v.y, h0, l0);
        split2(v.z, v.w, h1, l1);
        int c = r * SU + (c4 >> 1);
        yh[c] = h0; yh[c + 1] = h1;
        yl[c] = l0; yl[c + 1] = l1;
    }
    __syncthreads();

    // ldmatrix lane geometry: m0..m3 -> a0..a3 of m16n8k16 A-frag
    const int lrow = (lane & 7) + ((lane >> 3) & 1) * 8;
    const int lkof = (lane >> 4) * 16;                    // byte offset (+8 bf16 elems)
    const uint32_t yh_a = (uint32_t)__cvta_generic_to_shared(yh) + lrow * (SU * 4) + lkof;
    const uint32_t yl_a = (uint32_t)__cvta_generic_to_shared(yl) + lrow * (SU * 4) + lkof;
    const uint32_t hh_a = (uint32_t)__cvta_generic_to_shared(hh) + lrow * (SU * 4) + lkof;
    const uint32_t hl_a = (uint32_t)__cvta_generic_to_shared(hl) + lrow * (SU * 4) + lkof;

    float acc[2][4] = {};
    float dv0 = 0.f, dv1 = 0.f;

    for (int ch = 0; ch < 4; ch++) {
        // ---- Phase A: z = y @ W1 chunk (128 cols); warp owns 16 cols ----
        float z[2][4] = {};
        #pragma unroll
        for (int kt = 0; kt < 8; kt++) {
            uint32_t ah[4], al[4];
            ldsm4(ah, yh_a + kt * 32);
            ldsm4(al, yl_a + kt * 32);
            #pragma unroll
            for (int nt = 0; nt < 2; nt++) {
                int ntg = ch * 16 + warp * 2 + nt;
                uint4 w = g_W1p[(kt * 64 + ntg) * 32 + lane];
                mma_bf16(z[nt], ah, w.x, w.y);
                mma_bf16(z[nt], ah, w.z, w.w);
                mma_bf16(z[nt], al, w.x, w.y);
            }
        }

        // ---- tanh + divergence + bf16-split h into smem ----
        #pragma unroll
        for (int nt = 0; nt < 2; nt++) {
            int lc = warp * 16 + nt * 8 + tig * 2;
            int gc = ch * 128 + lc;
            float tb0 = g_tb[gc], tb1 = g_tb[gc + 1];
            float cc0 = g_c[gc],  cc1 = g_c[gc + 1];
            float h00 = tanhf(z[nt][0] + tb0);
            float h01 = tanhf(z[nt][1] + tb1);
            float h10 = tanhf(z[nt][2] + tb0);
            float h11 = tanhf(z[nt][3] + tb1);
            dv0 += cc0 * (1.f - h00 * h00) + cc1 * (1.f - h01 * h01);
            dv1 += cc0 * (1.f - h10 * h10) + cc1 * (1.f - h11 * h11);
            uint32_t ph, pl;
            split2(h00, h01, ph, pl);
            hh[gid * SU + (lc >> 1)] = ph;
            hl[gid * SU + (lc >> 1)] = pl;
            split2(h10, h11, ph, pl);
            hh[(gid + 8) * SU + (lc >> 1)] = ph;
            hl[(gid + 8) * SU + (lc >> 1)] = pl;
        }
        __syncthreads();

        // ---- Phase B: acc += h_chunk @ W2 rows; warp owns 16 D-cols ----
        #pragma unroll
        for (int kt = 0; kt < 8; kt++) {
            uint32_t ah[4], al[4];
            ldsm4(ah, hh_a + kt * 32);
            ldsm4(al, hl_a + kt * 32);
            int ktg = ch * 8 + kt;
            #pragma unroll
            for (int nt = 0; nt < 2; nt++) {
                int ntg = warp * 2 + nt;
                uint4 w = g_W2p[(ktg * 16 + ntg) * 32 + lane];
                mma_bf16(acc[nt], ah, w.x, w.y);
                mma_bf16(acc[nt], ah, w.z, w.w);
                mma_bf16(acc[nt], al, w.x, w.y);
            }
        }
        __syncthreads();   // protect hh/hl before next chunk overwrites
    }

    // ---- Epilogue: dy = acc + b2 ----
    #pragma unroll
    for (int nt = 0; nt < 2; nt++) {
        int col = warp * 16 + nt * 8 + tig * 2;
        float b20 = b2[col], b21 = b2[col + 1];
        float2 o0 = make_float2(acc[nt][0] + b20, acc[nt][1] + b21);
        float2 o1 = make_float2(acc[nt][2] + b20, acc[nt][3] + b21);
        *(float2*)(out + (size_t)(mb + gid) * D_ + col)     = o0;
        *(float2*)(out + (size_t)(mb + gid + 8) * D_ + col) = o1;
    }

    // ---- Divergence reduce ----
    dv0 += __shfl_xor_sync(0xFFFFFFFFu, dv0, 1);
    dv0 += __shfl_xor_sync(0xFFFFFFFFu, dv0, 2);
    dv1 += __shfl_xor_sync(0xFFFFFFFFu, dv1, 1);
    dv1 += __shfl_xor_sync(0xFFFFFFFFu, dv1, 2);
    if (tig == 0) {
        sdv[gid][warp]     = dv0;
        sdv[gid + 8][warp] = dv1;
    }
    __syncthreads();
    if (tid < BM) {
        float s = 0.f;
        #pragma unroll
        for (int w = 0; w < 8; w++) s += sdv[tid][w];
        out[(size_t)B_ * D_ + mb + tid] = -s;
    }
}

extern "C" void kernel_launch(void* const* d_in, const int* in_sizes, int n_in,
                              void* d_out, int out_size) {
    // Input order: t, y, logp, W1, b1, v1, W2, b2
    const float* t  = (const float*)d_in[0];
    const float* y  = (const float*)d_in[1];
    const float* W1 = (const float*)d_in[3];
    const float* b1 = (const float*)d_in[4];
    const float* v1 = (const float*)d_in[5];
    const float* W2 = (const float*)d_in[6];
    const float* b2 = (const float*)d_in[7];
    float* out = (float*)d_out;

    prep_kernel<<<16, 256>>>(t, W1, b1, v1, W2);
    pack_kernel<<<512, 256>>>(W1, W2);
    ode_kernel<<<B_ / BM, 256>>>(y, b2, out);
}

// round 6
// speedup vs baseline: 4.8069x; 1.0875x over previous
#include <cuda_runtime.h>
#include <cuda_bf16.h>
#include <cstdint>

// Problem: B=4096, D=128, H=512
//   z = y @ W1 + t*v1 + b1 ; h = tanh(z) ; dy = h @ W2 + b2
//   div[b] = sum_k (1 - h[b,k]^2) * c_k,  c_k = sum_i W1[i,k]*W2[k,i]
// Output: dy (B*D floats) then -div (B floats).
// GEMMs: mma m16n8k16 bf16, 3-term split (ahi*bhi + ahi*blo + alo*bhi), fp32 acc.
// BM=32 with in-warp m-replication: each B-fragment load feeds two m16 tiles.

#define B_ 4096
#define D_ 128
#define H_ 512
#define BM 32
#define SU 68   // smem row stride in uint32 (272B)

__device__ float g_c[H_];
__device__ float g_tb[H_];
__device__ uint4 g_W1p[512 * 32];   // kt<8 (D/16), nt<64 (H/8)
__device__ uint4 g_W2p[512 * 32];   // kt<32 (H/16), nt<16 (D/8)

__device__ __forceinline__ void split2(float a, float b, uint32_t& hi, uint32_t& lo) {
    __nv_bfloat16 ah = __float2bfloat16_rn(a);
    __nv_bfloat16 bh = __float2bfloat16_rn(b);
    __nv_bfloat16 al = __float2bfloat16_rn(a - __bfloat162float(ah));
    __nv_bfloat16 bl = __float2bfloat16_rn(b - __bfloat162float(bh));
    __nv_bfloat162 hp = __halves2bfloat162(ah, bh);
    __nv_bfloat162 lp = __halves2bfloat162(al, bl);
    hi = *reinterpret_cast<uint32_t*>(&hp);
    lo = *reinterpret_cast<uint32_t*>(&lp);
}

__device__ __forceinline__ void mma_bf16(float c[4], const uint32_t a[4],
                                         uint32_t b0, uint32_t b1) {
    asm volatile(
        "mma.sync.aligned.m16n8k16.row.col.f32.bf16.bf16.f32 "
        "{%0,%1,%2,%3}, {%4,%5,%6,%7}, {%8,%9}, {%0,%1,%2,%3};\n"
        : "+f"(c[0]), "+f"(c[1]), "+f"(c[2]), "+f"(c[3])
        : "r"(a[0]), "r"(a[1]), "r"(a[2]), "r"(a[3]), "r"(b0), "r"(b1));
}

__device__ __forceinline__ void ldsm4(uint32_t r[4], uint32_t addr) {
    asm volatile("ldmatrix.sync.aligned.m8n8.x4.shared.b16 {%0,%1,%2,%3}, [%4];"
                 : "=r"(r[0]), "=r"(r[1]), "=r"(r[2]), "=r"(r[3]) : "r"(addr));
}

// One block per H-column k; thread i does one product; tree-reduce.
__global__ __launch_bounds__(128) void prep_kernel(
    const float* __restrict__ t,  const float* __restrict__ W1,
    const float* __restrict__ b1, const float* __restrict__ v1,
    const float* __restrict__ W2) {
    __shared__ float red[4];
    const int k = blockIdx.x;
    const int i = threadIdx.x;
    float s = W1[(size_t)i * H_ + k] * W2[(size_t)k * D_ + i];
    #pragma unroll
    for (int off = 16; off > 0; off >>= 1)
        s += __shfl_xor_sync(0xFFFFFFFFu, s, off);
    if ((i & 31) == 0) red[i >> 5] = s;
    __syncthreads();
    if (i == 0) {
        g_c[k]  = red[0] + red[1] + red[2] + red[3];
        g_tb[k] = b1[k] + t[0] * v1[k];
    }
}

__global__ __launch_bounds__(256) void pack_kernel(
    const float* __restrict__ W1, const float* __restrict__ W2) {
    int idx  = blockIdx.x * 256 + threadIdx.x;   // 0..131071
    int comp = idx & 3;
    int lane = (idx >> 2) & 31;
    int frag = idx >> 7;
    int tig = lane & 3, gid = lane >> 2;
    int reg = comp & 1;
    bool ishi = comp < 2;
    float a, b;
    if (frag < 512) {  // W1: kt<8, nt<64
        int kt = frag >> 6, nt = frag & 63;
        int k0 = kt * 16 + 2 * tig + reg * 8;
        int n  = nt * 8 + gid;
        a = W1[(size_t)k0 * H_ + n];
        b = W1[(size_t)(k0 + 1) * H_ + n];
        uint32_t hi, lo; split2(a, b, hi, lo);
        ((uint32_t*)g_W1p)[frag * 128 + lane * 4 + comp] = ishi ? hi : lo;
    } else {           // W2: kt<32, nt<16
        int f2 = frag - 512;
        int kt = f2 >> 4, nt = f2 & 15;
        int k0 = kt * 16 + 2 * tig + reg * 8;
        int n  = nt * 8 + gid;
        a = W2[(size_t)k0 * D_ + n];
        b = W2[(size_t)(k0 + 1) * D_ + n];
        uint32_t hi, lo; split2(a, b, hi, lo);
        ((uint32_t*)g_W2p)[f2 * 128 + lane * 4 + comp] = ishi ? hi : lo;
    }
}

__global__ __launch_bounds__(256, 1) void ode_kernel(
    const float* __restrict__ y,
    const float* __restrict__ b2,
    float* __restrict__ out)
{
    __shared__ __align__(16) uint32_t yh[BM * SU], yl[BM * SU];
    __shared__ __align__(16) uint32_t hh[BM * SU], hl[BM * SU];
    __shared__ float sdv[BM][8];

    const int tid  = threadIdx.x;
    const int warp = tid >> 5;
    const int lane = tid & 31;
    const int gid  = lane >> 2;
    const int tig  = lane & 3;
    const int mb   = blockIdx.x * BM;

    // Load + bf16-split y tile (32 x 128)
    for (int i = tid; i < BM * 32; i += 256) {
        int r = i >> 5, c4 = (i & 31) * 4;
        float4 v = *(const float4*)(y + (size_t)(mb + r) * D_ + c4);
        uint32_t h0, l0, h1, l1;
        split2(v.x, v.y, h0, l0);
        split2(v.z, v.w, h1, l1);
        int c = r * SU + (c4 >> 1);
        yh[c] = h0; yh[c + 1] = h1;
        yl[c] = l0; yl[c + 1] = l1;
    }
    __syncthreads();

    const int lrow = (lane & 7) + ((lane >> 3) & 1) * 8;
    const int lkof = (lane >> 4) * 16;
    const uint32_t yh_a = (uint32_t)__cvta_generic_to_shared(yh) + lrow * (SU * 4) + lkof;
    const uint32_t yl_a = (uint32_t)__cvta_generic_to_shared(yl) + lrow * (SU * 4) + lkof;
    const uint32_t hh_a = (uint32_t)__cvta_generic_to_shared(hh) + lrow * (SU * 4) + lkof;
    const uint32_t hl_a = (uint32_t)__cvta_generic_to_shared(hl) + lrow * (SU * 4) + lkof;
    const uint32_t MOFF = 16 * (SU * 4);   // second m16 tile

    float acc[2][2][4] = {};   // [mt][nt][4]
    float dv[4] = {0.f, 0.f, 0.f, 0.f};

    for (int ch = 0; ch < 4; ch++) {
        // ---- Phase A: z = y @ W1 chunk; warp owns 16 n-cols, 32 m-rows ----
        float z[2][2][4] = {};
        #pragma unroll
        for (int kt = 0; kt < 8; kt++) {
            uint32_t ah0[4], al0[4], ah1[4], al1[4];
            ldsm4(ah0, yh_a + kt * 32);
            ldsm4(al0, yl_a + kt * 32);
            ldsm4(ah1, yh_a + MOFF + kt * 32);
            ldsm4(al1, yl_a + MOFF + kt * 32);
            #pragma unroll
            for (int nt = 0; nt < 2; nt++) {
                int ntg = ch * 16 + warp * 2 + nt;
                uint4 w = g_W1p[(kt * 64 + ntg) * 32 + lane];
                mma_bf16(z[0][nt], ah0, w.x, w.y);
                mma_bf16(z[0][nt], ah0, w.z, w.w);
                mma_bf16(z[0][nt], al0, w.x, w.y);
                mma_bf16(z[1][nt], ah1, w.x, w.y);
                mma_bf16(z[1][nt], ah1, w.z, w.w);
                mma_bf16(z[1][nt], al1, w.x, w.y);
            }
        }

        // ---- tanh + divergence + bf16-split h into smem ----
        #pragma unroll
        for (int mt = 0; mt < 2; mt++) {
            #pragma unroll
            for (int nt = 0; nt < 2; nt++) {
                int lc = warp * 16 + nt * 8 + tig * 2;
                int gc = ch * 128 + lc;
                float tb0 = g_tb[gc], tb1 = g_tb[gc + 1];
                float cc0 = g_c[gc],  cc1 = g_c[gc + 1];
                float h00 = tanhf(z[mt][nt][0] + tb0);
                float h01 = tanhf(z[mt][nt][1] + tb1);
                float h10 = tanhf(z[mt][nt][2] + tb0);
                float h11 = tanhf(z[mt][nt][3] + tb1);
                dv[mt * 2]     += cc0 * (1.f - h00 * h00) + cc1 * (1.f - h01 * h01);
                dv[mt * 2 + 1] += cc0 * (1.f - h10 * h10) + cc1 * (1.f - h11 * h11);
                uint32_t ph, pl;
                split2(h00, h01, ph, pl);
                hh[(gid + mt * 16) * SU + (lc >> 1)] = ph;
                hl[(gid + mt * 16) * SU + (lc >> 1)] = pl;
                split2(h10, h11, ph, pl);
                hh[(gid + 8 + mt * 16) * SU + (lc >> 1)] = ph;
                hl[(gid + 8 + mt * 16) * SU + (lc >> 1)] = pl;
            }
        }
        __syncthreads();

        // ---- Phase B: acc += h_chunk @ W2 rows ----
        #pragma unroll
        for (int kt = 0; kt < 8; kt++) {
            uint32_t ah0[4], al0[4], ah1[4], al1[4];
            ldsm4(ah0, hh_a + kt * 32);
            ldsm4(al0, hl_a + kt * 32);
            ldsm4(ah1, hh_a + MOFF + kt * 32);
            ldsm4(al1, hl_a + MOFF + kt * 32);
            int ktg = ch * 8 + kt;
            #pragma unroll
            for (int nt = 0; nt < 2; nt++) {
                int ntg = warp * 2 + nt;
                uint4 w = g_W2p[(ktg * 16 + ntg) * 32 + lane];
                mma_bf16(acc[0][nt], ah0, w.x, w.y);
                mma_bf16(acc[0][nt], ah0, w.z, w.w);
                mma_bf16(acc[0][nt], al0, w.x, w.y);
                mma_bf16(acc[1][nt], ah1, w.x, w.y);
                mma_bf16(acc[1][nt], ah1, w.z, w.w);
                mma_bf16(acc[1][nt], al1, w.x, w.y);
            }
        }
        __syncthreads();
    }

    // ---- Epilogue: dy = acc + b2 ----
    #pragma unroll
    for (int mt = 0; mt < 2; mt++) {
        #pragma unroll
        for (int nt = 0; nt < 2; nt++) {
            int col = warp * 16 + nt * 8 + tig * 2;
            float b20 = b2[col], b21 = b2[col + 1];
            float2 o0 = make_float2(acc[mt][nt][0] + b20, acc[mt][nt][1] + b21);
            float2 o1 = make_float2(acc[mt][nt][2] + b20, acc[mt][nt][3] + b21);
            *(float2*)(out + (size_t)(mb + gid + mt * 16) * D_ + col)     = o0;
            *(float2*)(out + (size_t)(mb + gid + 8 + mt * 16) * D_ + col) = o1;
        }
    }

    // ---- Divergence reduce ----
    #pragma unroll
    for (int j = 0; j < 4; j++) {
        dv[j] += __shfl_xor_sync(0xFFFFFFFFu, dv[j], 1);
        dv[j] += __shfl_xor_sync(0xFFFFFFFFu, dv[j], 2);
    }
    if (tig == 0) {
        sdv[gid][warp]      = dv[0];
        sdv[gid + 8][warp]  = dv[1];
        sdv[gid + 16][warp] = dv[2];
        sdv[gid + 24][warp] = dv[3];
    }
    __syncthreads();
    if (tid < BM) {
        float s = 0.f;
        #pragma unroll
        for (int w = 0; w < 8; w++) s += sdv[tid][w];
        out[(size_t)B_ * D_ + mb + tid] = -s;
    }
}

extern "C" void kernel_launch(void* const* d_in, const int* in_sizes, int n_in,
                              void* d_out, int out_size) {
    // Input order: t, y, logp, W1, b1, v1, W2, b2
    const float* t  = (const float*)d_in[0];
    const float* y  = (const float*)d_in[1];
    const float* W1 = (const float*)d_in[3];
    const float* b1 = (const float*)d_in[4];
    const float* v1 = (const float*)d_in[5];
    const float* W2 = (const float*)d_in[6];
    const float* b2 = (const float*)d_in[7];
    float* out = (float*)d_out;

    prep_kernel<<<H_, 128>>>(t, W1, b1, v1, W2);
    pack_kernel<<<512, 256>>>(W1, W2);
    ode_kernel<<<B_ / BM, 256>>>(y, b2, out);
}

// round 7
// speedup vs baseline: 5.2840x; 1.0992x over previous
#include <cuda_runtime.h>
#include <cuda_bf16.h>
#include <cstdint>

// Problem: B=4096, D=128, H=512
//   z = y @ W1 + t*v1 + b1 ; h = tanh(z) ; dy = h @ W2 + b2
//   div[b] = sum_k (1 - h[b,k]^2) * c_k,  c_k = sum_i W1[i,k]*W2[k,i]
// Output: dy (B*D floats) then -div (B floats).
// GEMMs: mma m16n8k16 bf16, 3-term split, fp32 acc. BM=32, in-warp m-replication.
// Setup (c_k/tb_k + weight fragment packing) fused into ONE kernel.

#define B_ 4096
#define D_ 128
#define H_ 512
#define BM 32
#define SU 68   // smem row stride in uint32 (272B)

__device__ float g_c[H_];
__device__ float g_tb[H_];
__device__ uint4 g_W1p[512 * 32];   // kt<8 (D/16), nt<64 (H/8)
__device__ uint4 g_W2p[512 * 32];   // kt<32 (H/16), nt<16 (D/8)

__device__ __forceinline__ void split2(float a, float b, uint32_t& hi, uint32_t& lo) {
    __nv_bfloat16 ah = __float2bfloat16_rn(a);
    __nv_bfloat16 bh = __float2bfloat16_rn(b);
    __nv_bfloat16 al = __float2bfloat16_rn(a - __bfloat162float(ah));
    __nv_bfloat16 bl = __float2bfloat16_rn(b - __bfloat162float(bh));
    __nv_bfloat162 hp = __halves2bfloat162(ah, bh);
    __nv_bfloat162 lp = __halves2bfloat162(al, bl);
    hi = *reinterpret_cast<uint32_t*>(&hp);
    lo = *reinterpret_cast<uint32_t*>(&lp);
}

__device__ __forceinline__ void mma_bf16(float c[4], const uint32_t a[4],
                                         uint32_t b0, uint32_t b1) {
    asm volatile(
        "mma.sync.aligned.m16n8k16.row.col.f32.bf16.bf16.f32 "
        "{%0,%1,%2,%3}, {%4,%5,%6,%7}, {%8,%9}, {%0,%1,%2,%3};\n"
        : "+f"(c[0]), "+f"(c[1]), "+f"(c[2]), "+f"(c[3])
        : "r"(a[0]), "r"(a[1]), "r"(a[2]), "r"(a[3]), "r"(b0), "r"(b1));
}

__device__ __forceinline__ void ldsm4(uint32_t r[4], uint32_t addr) {
    asm volatile("ldmatrix.sync.aligned.m8n8.x4.shared.b16 {%0,%1,%2,%3}, [%4];"
                 : "=r"(r[0]), "=r"(r[1]), "=r"(r[2]), "=r"(r[3]) : "r"(addr));
}

// Fused setup: blocks 0..511 pack weight fragments; blocks 512..1023 compute
// c_k and tb_k (one block per H-column, 128 active threads).
__global__ __launch_bounds__(256) void setup_kernel(
    const float* __restrict__ t,  const float* __restrict__ W1,
    const float* __restrict__ b1, const float* __restrict__ v1,
    const float* __restrict__ W2) {
    __shared__ float red[4];
    if (blockIdx.x < 512) {
        int idx  = blockIdx.x * 256 + threadIdx.x;   // 0..131071
        int comp = idx & 3;
        int lane = (idx >> 2) & 31;
        int frag = idx >> 7;
        int tig = lane & 3, gid = lane >> 2;
        int reg = comp & 1;
        bool ishi = comp < 2;
        float a, b;
        if (frag < 512) {  // W1: kt<8, nt<64
            int kt = frag >> 6, nt = frag & 63;
            int k0 = kt * 16 + 2 * tig + reg * 8;
            int n  = nt * 8 + gid;
            a = W1[(size_t)k0 * H_ + n];
            b = W1[(size_t)(k0 + 1) * H_ + n];
            uint32_t hi, lo; split2(a, b, hi, lo);
            ((uint32_t*)g_W1p)[frag * 128 + lane * 4 + comp] = ishi ? hi : lo;
        } else {           // W2: kt<32, nt<16
            int f2 = frag - 512;
            int kt = f2 >> 4, nt = f2 & 15;
            int k0 = kt * 16 + 2 * tig + reg * 8;
            int n  = nt * 8 + gid;
            a = W2[(size_t)k0 * D_ + n];
            b = W2[(size_t)(k0 + 1) * D_ + n];
            uint32_t hi, lo; split2(a, b, hi, lo);
            ((uint32_t*)g_W2p)[f2 * 128 + lane * 4 + comp] = ishi ? hi : lo;
        }
    } else {
        const int k = blockIdx.x - 512;
        const int i = threadIdx.x;
        if (i < 128) {
            float s = W1[(size_t)i * H_ + k] * W2[(size_t)k * D_ + i];
            #pragma unroll
            for (int off = 16; off > 0; off >>= 1)
                s += __shfl_xor_sync(0xFFFFFFFFu, s, off);
            if ((i & 31) == 0) red[i >> 5] = s;
        }
        __syncthreads();
        if (i == 0) {
            g_c[k]  = red[0] + red[1] + red[2] + red[3];
            g_tb[k] = b1[k] + t[0] * v1[k];
        }
    }
}

__global__ __launch_bounds__(256, 1) void ode_kernel(
    const float* __restrict__ y,
    const float* __restrict__ b2,
    float* __restrict__ out)
{
    __shared__ __align__(16) uint32_t yh[BM * SU], yl[BM * SU];
    __shared__ __align__(16) uint32_t hh[BM * SU], hl[BM * SU];
    __shared__ float sdv[BM][8];

    const int tid  = threadIdx.x;
    const int warp = tid >> 5;
    const int lane = tid & 31;
    const int gid  = lane >> 2;
    const int tig  = lane & 3;
    const int mb   = blockIdx.x * BM;

    // Load + bf16-split y tile (32 x 128)
    for (int i = tid; i < BM * 32; i += 256) {
        int r = i >> 5, c4 = (i & 31) * 4;
        float4 v = *(const float4*)(y + (size_t)(mb + r) * D_ + c4);
        uint32_t h0, l0, h1, l1;
        split2(v.x, v.y, h0, l0);
        split2(v.z, v.w, h1, l1);
        int c = r * SU + (c4 >> 1);
        yh[c] = h0; yh[c + 1] = h1;
        yl[c] = l0; yl[c + 1] = l1;
    }
    __syncthreads();

    const int lrow = (lane & 7) + ((lane >> 3) & 1) * 8;
    const int lkof = (lane >> 4) * 16;
    const uint32_t yh_a = (uint32_t)__cvta_generic_to_shared(yh) + lrow * (SU * 4) + lkof;
    const uint32_t yl_a = (uint32_t)__cvta_generic_to_shared(yl) + lrow * (SU * 4) + lkof;
    const uint32_t hh_a = (uint32_t)__cvta_generic_to_shared(hh) + lrow * (SU * 4) + lkof;
    const uint32_t hl_a = (uint32_t)__cvta_generic_to_shared(hl) + lrow * (SU * 4) + lkof;
    const uint32_t MOFF = 16 * (SU * 4);   // second m16 tile

    float acc[2][2][4] = {};   // [mt][nt][4]
    float dv[4] = {0.f, 0.f, 0.f, 0.f};

    for (int ch = 0; ch < 4; ch++) {
        // ---- Phase A: z = y @ W1 chunk; warp owns 16 n-cols, 32 m-rows ----
        float z[2][2][4] = {};
        #pragma unroll
        for (int kt = 0; kt < 8; kt++) {
            uint32_t ah0[4], al0[4], ah1[4], al1[4];
            ldsm4(ah0, yh_a + kt * 32);
            ldsm4(al0, yl_a + kt * 32);
            ldsm4(ah1, yh_a + MOFF + kt * 32);
            ldsm4(al1, yl_a + MOFF + kt * 32);
            #pragma unroll
            for (int nt = 0; nt < 2; nt++) {
                int ntg = ch * 16 + warp * 2 + nt;
                uint4 w = g_W1p[(kt * 64 + ntg) * 32 + lane];
                mma_bf16(z[0][nt], ah0, w.x, w.y);
                mma_bf16(z[0][nt], ah0, w.z, w.w);
                mma_bf16(z[0][nt], al0, w.x, w.y);
                mma_bf16(z[1][nt], ah1, w.x, w.y);
                mma_bf16(z[1][nt], ah1, w.z, w.w);
                mma_bf16(z[1][nt], al1, w.x, w.y);
            }
        }

        // ---- tanh + divergence + bf16-split h into smem ----
        #pragma unroll
        for (int mt = 0; mt < 2; mt++) {
            #pragma unroll
            for (int nt = 0; nt < 2; nt++) {
                int lc = warp * 16 + nt * 8 + tig * 2;
                int gc = ch * 128 + lc;
                float tb0 = g_tb[gc], tb1 = g_tb[gc + 1];
                float cc0 = g_c[gc],  cc1 = g_c[gc + 1];
                float h00 = tanhf(z[mt][nt][0] + tb0);
                float h01 = tanhf(z[mt][nt][1] + tb1);
                float h10 = tanhf(z[mt][nt][2] + tb0);
                float h11 = tanhf(z[mt][nt][3] + tb1);
                dv[mt * 2]     += cc0 * (1.f - h00 * h00) + cc1 * (1.f - h01 * h01);
                dv[mt * 2 + 1] += cc0 * (1.f - h10 * h10) + cc1 * (1.f - h11 * h11);
                uint32_t ph, pl;
                split2(h00, h01, ph, pl);
                hh[(gid + mt * 16) * SU + (lc >> 1)] = ph;
                hl[(gid + mt * 16) * SU + (lc >> 1)] = pl;
                split2(h10, h11, ph, pl);
                hh[(gid + 8 + mt * 16) * SU + (lc >> 1)] = ph;
                hl[(gid + 8 + mt * 16) * SU + (lc >> 1)] = pl;
            }
        }
        __syncthreads();

        // ---- Phase B: acc += h_chunk @ W2 rows ----
        #pragma unroll
        for (int kt = 0; kt < 8; kt++) {
            uint32_t ah0[4], al0[4], ah1[4], al1[4];
            ldsm4(ah0, hh_a + kt * 32);
            ldsm4(al0, hl_a + kt * 32);
            ldsm4(ah1, hh_a + MOFF + kt * 32);
            ldsm4(al1, hl_a + MOFF + kt * 32);
            int ktg = ch * 8 + kt;
            #pragma unroll
            for (int nt = 0; nt < 2; nt++) {
                int ntg = warp * 2 + nt;
                uint4 w = g_W2p[(ktg * 16 + ntg) * 32 + lane];
                mma_bf16(acc[0][nt], ah0, w.x, w.y);
                mma_bf16(acc[0][nt], ah0, w.z, w.w);
                mma_bf16(acc[0][nt], al0, w.x, w.y);
                mma_bf16(acc[1][nt], ah1, w.x, w.y);
                mma_bf16(acc[1][nt], ah1, w.z, w.w);
                mma_bf16(acc[1][nt], al1, w.x, w.y);
            }
        }
        __syncthreads();
    }

    // ---- Epilogue: dy = acc + b2 ----
    #pragma unroll
    for (int mt = 0; mt < 2; mt++) {
        #pragma unroll
        for (int nt = 0; nt < 2; nt++) {
            int col = warp * 16 + nt * 8 + tig * 2;
            float b20 = b2[col], b21 = b2[col + 1];
            float2 o0 = make_float2(acc[mt][nt][0] + b20, acc[mt][nt][1] + b21);
            float2 o1 = make_float2(acc[mt][nt][2] + b20, acc[mt][nt][3] + b21);
            *(float2*)(out + (size_t)(mb + gid + mt * 16) * D_ + col)     = o0;
            *(float2*)(out + (size_t)(mb + gid + 8 + mt * 16) * D_ + col) = o1;
        }
    }

    // ---- Divergence reduce ----
    #pragma unroll
    for (int j = 0; j < 4; j++) {
        dv[j] += __shfl_xor_sync(0xFFFFFFFFu, dv[j], 1);
        dv[j] += __shfl_xor_sync(0xFFFFFFFFu, dv[j], 2);
    }
    if (tig == 0) {
        sdv[gid][warp]      = dv[0];
        sdv[gid + 8][warp]  = dv[1];
        sdv[gid + 16][warp] = dv[2];
        sdv[gid + 24][warp] = dv[3];
    }
    __syncthreads();
    if (tid < BM) {
        float s = 0.f;
        #pragma unroll
        for (int w = 0; w < 8; w++) s += sdv[tid][w];
        out[(size_t)B_ * D_ + mb + tid] = -s;
    }
}

extern "C" void kernel_launch(void* const* d_in, const int* in_sizes, int n_in,
                              void* d_out, int out_size) {
    // Input order: t, y, logp, W1, b1, v1, W2, b2
    const float* t  = (const float*)d_in[0];
    const float* y  = (const float*)d_in[1];
    const float* W1 = (const float*)d_in[3];
    const float* b1 = (const float*)d_in[4];
    const float* v1 = (const float*)d_in[5];
    const float* W2 = (const float*)d_in[6];
    const float* b2 = (const float*)d_in[7];
    float* out = (float*)d_out;

    setup_kernel<<<1024, 256>>>(t, W1, b1, v1, W2);
    ode_kernel<<<B_ / BM, 256>>>(y, b2, out);
}

// round 8
// speedup vs baseline: 5.4418x; 1.0299x over previous
#include <cuda_runtime.h>
#include <cuda_bf16.h>
#include <cstdint>

// Problem: B=4096, D=128, H=512
//   z = y @ W1 + t*v1 + b1 ; h = tanh(z) ; dy = h @ W2 + b2
//   div[b] = sum_k (1 - h[b,k]^2) * c_k,  c_k = sum_i W1[i,k]*W2[k,i]
// Output: dy (B*D floats) then -div (B floats).
// GEMMs: mma m16n8k16 bf16, 3-term split (ahi*bhi + ahi*blo + alo*bhi), fp32 acc.
// BM=16, 2 CTAs/SM (occupancy-optimized). Single fused setup kernel.

#define B_ 4096
#define D_ 128
#define H_ 512
#define BM 16
#define SU 68   // smem row stride in uint32 (272B)

__device__ float g_c[H_];
__device__ float g_tb[H_];
__device__ uint4 g_W1p[512 * 32];   // kt<8 (D/16), nt<64 (H/8)
__device__ uint4 g_W2p[512 * 32];   // kt<32 (H/16), nt<16 (D/8)

__device__ __forceinline__ void split2(float a, float b, uint32_t& hi, uint32_t& lo) {
    __nv_bfloat16 ah = __float2bfloat16_rn(a);
    __nv_bfloat16 bh = __float2bfloat16_rn(b);
    __nv_bfloat16 al = __float2bfloat16_rn(a - __bfloat162float(ah));
    __nv_bfloat16 bl = __float2bfloat16_rn(b - __bfloat162float(bh));
    __nv_bfloat162 hp = __halves2bfloat162(ah, bh);
    __nv_bfloat162 lp = __halves2bfloat162(al, bl);
    hi = *reinterpret_cast<uint32_t*>(&hp);
    lo = *reinterpret_cast<uint32_t*>(&lp);
}

__device__ __forceinline__ void mma_bf16(float c[4], const uint32_t a[4],
                                         uint32_t b0, uint32_t b1) {
    asm volatile(
        "mma.sync.aligned.m16n8k16.row.col.f32.bf16.bf16.f32 "
        "{%0,%1,%2,%3}, {%4,%5,%6,%7}, {%8,%9}, {%0,%1,%2,%3};\n"
        : "+f"(c[0]), "+f"(c[1]), "+f"(c[2]), "+f"(c[3])
        : "r"(a[0]), "r"(a[1]), "r"(a[2]), "r"(a[3]), "r"(b0), "r"(b1));
}

__device__ __forceinline__ void ldsm4(uint32_t r[4], uint32_t addr) {
    asm volatile("ldmatrix.sync.aligned.m8n8.x4.shared.b16 {%0,%1,%2,%3}, [%4];"
                 : "=r"(r[0]), "=r"(r[1]), "=r"(r[2]), "=r"(r[3]) : "r"(addr));
}

// Fused setup: blocks 0..511 pack weight fragments; blocks 512..1023 compute
// c_k and tb_k (one block per H-column, 128 active threads).
__global__ __launch_bounds__(256) void setup_kernel(
    const float* __restrict__ t,  const float* __restrict__ W1,
    const float* __restrict__ b1, const float* __restrict__ v1,
    const float* __restrict__ W2) {
    __shared__ float red[4];
    if (blockIdx.x < 512) {
        int idx  = blockIdx.x * 256 + threadIdx.x;   // 0..131071
        int comp = idx & 3;
        int lane = (idx >> 2) & 31;
        int frag = idx >> 7;
        int tig = lane & 3, gid = lane >> 2;
        int reg = comp & 1;
        bool ishi = comp < 2;
        float a, b;
        if (frag < 512) {  // W1: kt<8, nt<64
            int kt = frag >> 6, nt = frag & 63;
            int k0 = kt * 16 + 2 * tig + reg * 8;
            int n  = nt * 8 + gid;
            a = W1[(size_t)k0 * H_ + n];
            b = W1[(size_t)(k0 + 1) * H_ + n];
            uint32_t hi, lo; split2(a, b, hi, lo);
            ((uint32_t*)g_W1p)[frag * 128 + lane * 4 + comp] = ishi ? hi : lo;
        } else {           // W2: kt<32, nt<16
            int f2 = frag - 512;
            int kt = f2 >> 4, nt = f2 & 15;
            int k0 = kt * 16 + 2 * tig + reg * 8;
            int n  = nt * 8 + gid;
            a = W2[(size_t)k0 * D_ + n];
            b = W2[(size_t)(k0 + 1) * D_ + n];
            uint32_t hi, lo; split2(a, b, hi, lo);
            ((uint32_t*)g_W2p)[f2 * 128 + lane * 4 + comp] = ishi ? hi : lo;
        }
    } else {
        const int k = blockIdx.x - 512;
        const int i = threadIdx.x;
        if (i < 128) {
            float s = W1[(size_t)i * H_ + k] * W2[(size_t)k * D_ + i];
            #pragma unroll
            for (int off = 16; off > 0; off >>= 1)
                s += __shfl_xor_sync(0xFFFFFFFFu, s, off);
            if ((i & 31) == 0) red[i >> 5] = s;
        }
        __syncthreads();
        if (i == 0) {
            g_c[k]  = red[0] + red[1] + red[2] + red[3];
            g_tb[k] = b1[k] + t[0] * v1[k];
        }
    }
}

__global__ __launch_bounds__(256, 2) void ode_kernel(
    const float* __restrict__ y,
    const float* __restrict__ b2,
    float* __restrict__ out)
{
    __shared__ __align__(16) uint32_t yh[BM * SU], yl[BM * SU];
    __shared__ __align__(16) uint32_t hh[BM * SU], hl[BM * SU];
    __shared__ float sdv[BM][8];

    const int tid  = threadIdx.x;
    const int warp = tid >> 5;
    const int lane = tid & 31;
    const int gid  = lane >> 2;
    const int tig  = lane & 3;
    const int mb   = blockIdx.x * BM;

    // Load + bf16-split y tile (16 x 128)
    for (int i = tid; i < BM * 32; i += 256) {
        int r = i >> 5, c4 = (i & 31) * 4;
        float4 v = *(const float4*)(y + (size_t)(mb + r) * D_ + c4);
        uint32_t h0, l0, h1, l1;
        split2(v.x, v.y, h0, l0);
        split2(v.z, v.w, h1, l1);
        int c = r * SU + (c4 >> 1);
        yh[c] = h0; yh[c + 1] = h1;
        yl[c] = l0; yl[c + 1] = l1;
    }
    __syncthreads();

    const int lrow = (lane & 7) + ((lane >> 3) & 1) * 8;
    const int lkof = (lane >> 4) * 16;
    const uint32_t yh_a = (uint32_t)__cvta_generic_to_shared(yh) + lrow * (SU * 4) + lkof;
    const uint32_t yl_a = (uint32_t)__cvta_generic_to_shared(yl) + lrow * (SU * 4) + lkof;
    const uint32_t hh_a = (uint32_t)__cvta_generic_to_shared(hh) + lrow * (SU * 4) + lkof;
    const uint32_t hl_a = (uint32_t)__cvta_generic_to_shared(hl) + lrow * (SU * 4) + lkof;

    float acc[2][4] = {};
    float dv0 = 0.f, dv1 = 0.f;

    for (int ch = 0; ch < 4; ch++) {
        // ---- Phase A: z = y @ W1 chunk (128 cols); warp owns 16 cols ----
        float z[2][4] = {};
        #pragma unroll
        for (int kt = 0; kt < 8; kt++) {
            uint32_t ah[4], al[4];
            ldsm4(ah, yh_a + kt * 32);
            ldsm4(al, yl_a + kt * 32);
            #pragma unroll
            for (int nt = 0; nt < 2; nt++) {
                int ntg = ch * 16 + warp * 2 + nt;
                uint4 w = g_W1p[(kt * 64 + ntg) * 32 + lane];
                mma_bf16(z[nt], ah, w.x, w.y);
                mma_bf16(z[nt], ah, w.z, w.w);
                mma_bf16(z[nt], al, w.x, w.y);
            }
        }

        // ---- tanh + divergence + bf16-split h into smem ----
        #pragma unroll
        for (int nt = 0; nt < 2; nt++) {
            int lc = warp * 16 + nt * 8 + tig * 2;
            int gc = ch * 128 + lc;
            float tb0 = g_tb[gc], tb1 = g_tb[gc + 1];
            float cc0 = g_c[gc],  cc1 = g_c[gc + 1];
            float h00 = tanhf(z[nt][0] + tb0);
            float h01 = tanhf(z[nt][1] + tb1);
            float h10 = tanhf(z[nt][2] + tb0);
            float h11 = tanhf(z[nt][3] + tb1);
            dv0 += cc0 * (1.f - h00 * h00) + cc1 * (1.f - h01 * h01);
            dv1 += cc0 * (1.f - h10 * h10) + cc1 * (1.f - h11 * h11);
            uint32_t ph, pl;
            split2(h00, h01, ph, pl);
            hh[gid * SU + (lc >> 1)] = ph;
            hl[gid * SU + (lc >> 1)] = pl;
            split2(h10, h11, ph, pl);
            hh[(gid + 8) * SU + (lc >> 1)] = ph;
            hl[(gid + 8) * SU + (lc >> 1)] = pl;
        }
        __syncthreads();

        // ---- Phase B: acc += h_chunk @ W2 rows; warp owns 16 D-cols ----
        #pragma unroll
        for (int kt = 0; kt < 8; kt++) {
            uint32_t ah[4], al[4];
            ldsm4(ah, hh_a + kt * 32);
            ldsm4(al, hl_a + kt * 32);
            int ktg = ch * 8 + kt;
            #pragma unroll
            for (int nt = 0; nt < 2; nt++) {
                int ntg = warp * 2 + nt;
                uint4 w = g_W2p[(ktg * 16 + ntg) * 32 + lane];
                mma_bf16(acc[nt], ah, w.x, w.y);
                mma_bf16(acc[nt], ah, w.z, w.w);
                mma_bf16(acc[nt], al, w.x, w.y);
            }
        }
        __syncthreads();   // protect hh/hl before next chunk overwrites
    }

    // ---- Epilogue: dy = acc + b2 ----
    #pragma unroll
    for (int nt = 0; nt < 2; nt++) {
        int col = warp * 16 + nt * 8 + tig * 2;
        float b20 = b2[col], b21 = b2[col + 1];
        float2 o0 = make_float2(acc[nt][0] + b20, acc[nt][1] + b21);
        float2 o1 = make_float2(acc[nt][2] + b20, acc[nt][3] + b21);
        *(float2*)(out + (size_t)(mb + gid) * D_ + col)     = o0;
        *(float2*)(out + (size_t)(mb + gid + 8) * D_ + col) = o1;
    }

    // ---- Divergence reduce ----
    dv0 += __shfl_xor_sync(0xFFFFFFFFu, dv0, 1);
    dv0 += __shfl_xor_sync(0xFFFFFFFFu, dv0, 2);
    dv1 += __shfl_xor_sync(0xFFFFFFFFu, dv1, 1);
    dv1 += __shfl_xor_sync(0xFFFFFFFFu, dv1, 2);
    if (tig == 0) {
        sdv[gid][warp]     = dv0;
        sdv[gid + 8][warp] = dv1;
    }
    __syncthreads();
    if (tid < BM) {
        float s = 0.f;
        #pragma unroll
        for (int w = 0; w < 8; w++) s += sdv[tid][w];
        out[(size_t)B_ * D_ + mb + tid] = -s;
    }
}

extern "C" void kernel_launch(void* const* d_in, const int* in_sizes, int n_in,
                              void* d_out, int out_size) {
    // Input order: t, y, logp, W1, b1, v1, W2, b2
    const float* t  = (const float*)d_in[0];
    const float* y  = (const float*)d_in[1];
    const float* W1 = (const float*)d_in[3];
    const float* b1 = (const float*)d_in[4];
    const float* v1 = (const float*)d_in[5];
    const float* W2 = (const float*)d_in[6];
    const float* b2 = (const float*)d_in[7];
    float* out = (float*)d_out;

    setup_kernel<<<1024, 256>>>(t, W1, b1, v1, W2);
    ode_kernel<<<B_ / BM, 256>>>(y, b2, out);
}

// round 9
// speedup vs baseline: 5.8562x; 1.0761x over previous
#include <cuda_runtime.h>
#include <cuda_bf16.h>
#include <cstdint>

// Problem: B=4096, D=128, H=512
//   z = y @ W1 + t*v1 + b1 ; h = tanh(z) ; dy = h @ W2 + b2
//   div[b] = sum_k (1 - h[b,k]^2) * c_k,  c_k = sum_i W1[i,k]*W2[k,i]
// Output: dy (B*D floats) then -div (B floats).
// mma m16n8k16 bf16, 3-term split, fp32 acc. BM=16, 2 CTAs/SM.
// Monolithic phases: full z (H=512) in registers -> tanh -> ONE sync -> full dy GEMM.

#define B_ 4096
#define D_ 128
#define H_ 512
#define BM 16
#define SU 68    // y smem row stride in uint32 (272B), mod 32 = 4 -> ldsm conflict-free
#define HSU 260  // h smem row stride in uint32 (1040B), mod 32 = 4 -> conflict-free

__device__ float g_c[H_];
__device__ float g_tb[H_];
__device__ uint4 g_W1p[512 * 32];   // kt<8 (D/16), nt<64 (H/8)
__device__ uint4 g_W2p[512 * 32];   // kt<32 (H/16), nt<16 (D/8)

__device__ __forceinline__ void split2(float a, float b, uint32_t& hi, uint32_t& lo) {
    __nv_bfloat16 ah = __float2bfloat16_rn(a);
    __nv_bfloat16 bh = __float2bfloat16_rn(b);
    __nv_bfloat16 al = __float2bfloat16_rn(a - __bfloat162float(ah));
    __nv_bfloat16 bl = __float2bfloat16_rn(b - __bfloat162float(bh));
    __nv_bfloat162 hp = __halves2bfloat162(ah, bh);
    __nv_bfloat162 lp = __halves2bfloat162(al, bl);
    hi = *reinterpret_cast<uint32_t*>(&hp);
    lo = *reinterpret_cast<uint32_t*>(&lp);
}

__device__ __forceinline__ void mma_bf16(float c[4], const uint32_t a[4],
                                         uint32_t b0, uint32_t b1) {
    asm volatile(
        "mma.sync.aligned.m16n8k16.row.col.f32.bf16.bf16.f32 "
        "{%0,%1,%2,%3}, {%4,%5,%6,%7}, {%8,%9}, {%0,%1,%2,%3};\n"
        : "+f"(c[0]), "+f"(c[1]), "+f"(c[2]), "+f"(c[3])
        : "r"(a[0]), "r"(a[1]), "r"(a[2]), "r"(a[3]), "r"(b0), "r"(b1));
}

__device__ __forceinline__ void ldsm4(uint32_t r[4], uint32_t addr) {
    asm volatile("ldmatrix.sync.aligned.m8n8.x4.shared.b16 {%0,%1,%2,%3}, [%4];"
                 : "=r"(r[0]), "=r"(r[1]), "=r"(r[2]), "=r"(r[3]) : "r"(addr));
}

// Fused setup: blocks 0..511 pack weight fragments; blocks 512..1023 compute c_k/tb_k.
__global__ __launch_bounds__(256) void setup_kernel(
    const float* __restrict__ t,  const float* __restrict__ W1,
    const float* __restrict__ b1, const float* __restrict__ v1,
    const float* __restrict__ W2) {
    __shared__ float red[4];
    if (blockIdx.x < 512) {
        int idx  = blockIdx.x * 256 + threadIdx.x;
        int comp = idx & 3;
        int lane = (idx >> 2) & 31;
        int frag = idx >> 7;
        int tig = lane & 3, gid = lane >> 2;
        int reg = comp & 1;
        bool ishi = comp < 2;
        float a, b;
        if (frag < 512) {  // W1
            int kt = frag >> 6, nt = frag & 63;
            int k0 = kt * 16 + 2 * tig + reg * 8;
            int n  = nt * 8 + gid;
            a = W1[(size_t)k0 * H_ + n];
            b = W1[(size_t)(k0 + 1) * H_ + n];
            uint32_t hi, lo; split2(a, b, hi, lo);
            ((uint32_t*)g_W1p)[frag * 128 + lane * 4 + comp] = ishi ? hi : lo;
        } else {           // W2
            int f2 = frag - 512;
            int kt = f2 >> 4, nt = f2 & 15;
            int k0 = kt * 16 + 2 * tig + reg * 8;
            int n  = nt * 8 + gid;
            a = W2[(size_t)k0 * D_ + n];
            b = W2[(size_t)(k0 + 1) * D_ + n];
            uint32_t hi, lo; split2(a, b, hi, lo);
            ((uint32_t*)g_W2p)[f2 * 128 + lane * 4 + comp] = ishi ? hi : lo;
        }
    } else {
        const int k = blockIdx.x - 512;
        const int i = threadIdx.x;
        if (i < 128) {
            float s = W1[(size_t)i * H_ + k] * W2[(size_t)k * D_ + i];
            #pragma unroll
            for (int off = 16; off > 0; off >>= 1)
                s += __shfl_xor_sync(0xFFFFFFFFu, s, off);
            if ((i & 31) == 0) red[i >> 5] = s;
        }
        __syncthreads();
        if (i == 0) {
            g_c[k]  = red[0] + red[1] + red[2] + red[3];
            g_tb[k] = b1[k] + t[0] * v1[k];
        }
    }
}

__global__ __launch_bounds__(256, 2) void ode_kernel(
    const float* __restrict__ y,
    const float* __restrict__ b2,
    float* __restrict__ out)
{
    __shared__ __align__(16) uint32_t yh[BM * SU], yl[BM * SU];
    __shared__ __align__(16) uint32_t hh[BM * HSU], hl[BM * HSU];
    __shared__ float sdv[BM][8];

    const int tid  = threadIdx.x;
    const int warp = tid >> 5;
    const int lane = tid & 31;
    const int gid  = lane >> 2;
    const int tig  = lane & 3;
    const int mb   = blockIdx.x * BM;

    // Load + bf16-split y tile (16 x 128)
    for (int i = tid; i < BM * 32; i += 256) {
        int r = i >> 5, c4 = (i & 31) * 4;
        float4 v = *(const float4*)(y + (size_t)(mb + r) * D_ + c4);
        uint32_t h0, l0, h1, l1;
        split2(v.x, v.y, h0, l0);
        split2(v.z, v.w, h1, l1);
        int c = r * SU + (c4 >> 1);
        yh[c] = h0; yh[c + 1] = h1;
        yl[c] = l0; yl[c + 1] = l1;
    }
    __syncthreads();

    const int lrow = (lane & 7) + ((lane >> 3) & 1) * 8;
    const int lkof = (lane >> 4) * 16;
    const uint32_t yh_a = (uint32_t)__cvta_generic_to_shared(yh) + lrow * (SU * 4) + lkof;
    const uint32_t yl_a = (uint32_t)__cvta_generic_to_shared(yl) + lrow * (SU * 4) + lkof;
    const uint32_t hh_a = (uint32_t)__cvta_generic_to_shared(hh) + lrow * (HSU * 4) + lkof;
    const uint32_t hl_a = (uint32_t)__cvta_generic_to_shared(hl) + lrow * (HSU * 4) + lkof;

    // ---- Phase A: z = y @ W1 for ALL 512 cols; warp owns 64 cols (4 chunks x 16) ----
    float z[4][2][4] = {};   // [ch][nt][4]
    #pragma unroll
    for (int kt = 0; kt < 8; kt++) {
        uint32_t ah[4], al[4];
        ldsm4(ah, yh_a + kt * 32);
        ldsm4(al, yl_a + kt * 32);
        #pragma unroll
        for (int ch = 0; ch < 4; ch++) {
            #pragma unroll
            for (int nt = 0; nt < 2; nt++) {
                int ntg = ch * 16 + warp * 2 + nt;
                uint4 w = g_W1p[(kt * 64 + ntg) * 32 + lane];
                mma_bf16(z[ch][nt], ah, w.x, w.y);
                mma_bf16(z[ch][nt], ah, w.z, w.w);
                mma_bf16(z[ch][nt], al, w.x, w.y);
            }
        }
    }

    // ---- tanh + divergence + bf16-split h into smem (all 512 cols) ----
    float dv0 = 0.f, dv1 = 0.f;
    #pragma unroll
    for (int ch = 0; ch < 4; ch++) {
        #pragma unroll
        for (int nt = 0; nt < 2; nt++) {
            int gc = ch * 128 + warp * 16 + nt * 8 + tig * 2;   // global H col
            float tb0 = g_tb[gc], tb1 = g_tb[gc + 1];
            float cc0 = g_c[gc],  cc1 = g_c[gc + 1];
            float h00 = tanhf(z[ch][nt][0] + tb0);
            float h01 = tanhf(z[ch][nt][1] + tb1);
            float h10 = tanhf(z[ch][nt][2] + tb0);
            float h11 = tanhf(z[ch][nt][3] + tb1);
            dv0 += cc0 * (1.f - h00 * h00) + cc1 * (1.f - h01 * h01);
            dv1 += cc0 * (1.f - h10 * h10) + cc1 * (1.f - h11 * h11);
            uint32_t ph, pl;
            split2(h00, h01, ph, pl);
            hh[gid * HSU + (gc >> 1)] = ph;
            hl[gid * HSU + (gc >> 1)] = pl;
            split2(h10, h11, ph, pl);
            hh[(gid + 8) * HSU + (gc >> 1)] = ph;
            hl[(gid + 8) * HSU + (gc >> 1)] = pl;
        }
    }
    __syncthreads();

    // ---- Phase B: dy = h @ W2 over ALL 512 k; warp owns 16 D-cols ----
    float acc[2][4] = {};
    #pragma unroll
    for (int ktg = 0; ktg < 32; ktg++) {
        uint32_t ah[4], al[4];
        ldsm4(ah, hh_a + ktg * 32);
        ldsm4(al, hl_a + ktg * 32);
        #pragma unroll
        for (int nt = 0; nt < 2; nt++) {
            int ntg = warp * 2 + nt;
            uint4 w = g_W2p[(ktg * 16 + ntg) * 32 + lane];
            mma_bf16(acc[nt], ah, w.x, w.y);
            mma_bf16(acc[nt], ah, w.z, w.w);
            mma_bf16(acc[nt], al, w.x, w.y);
        }
    }

    // ---- Epilogue: dy = acc + b2 ----
    #pragma unroll
    for (int nt = 0; nt < 2; nt++) {
        int col = warp * 16 + nt * 8 + tig * 2;
        float b20 = b2[col], b21 = b2[col + 1];
        float2 o0 = make_float2(acc[nt][0] + b20, acc[nt][1] + b21);
        float2 o1 = make_float2(acc[nt][2] + b20, acc[nt][3] + b21);
        *(float2*)(out + (size_t)(mb + gid) * D_ + col)     = o0;
        *(float2*)(out + (size_t)(mb + gid + 8) * D_ + col) = o1;
    }

    // ---- Divergence reduce ----
    dv0 += __shfl_xor_sync(0xFFFFFFFFu, dv0, 1);
    dv0 += __shfl_xor_sync(0xFFFFFFFFu, dv0, 2);
    dv1 += __shfl_xor_sync(0xFFFFFFFFu, dv1, 1);
    dv1 += __shfl_xor_sync(0xFFFFFFFFu, dv1, 2);
    if (tig == 0) {
        sdv[gid][warp]     = dv0;
        sdv[gid + 8][warp] = dv1;
    }
    __syncthreads();
    if (tid < BM) {
        float s = 0.f;
        #pragma unroll
        for (int w = 0; w < 8; w++) s += sdv[tid][w];
        out[(size_t)B_ * D_ + mb + tid] = -s;
    }
}

extern "C" void kernel_launch(void* const* d_in, const int* in_sizes, int n_in,
                              void* d_out, int out_size) {
    // Input order: t, y, logp, W1, b1, v1, W2, b2
    const float* t  = (const float*)d_in[0];
    const float* y  = (const float*)d_in[1];
    const float* W1 = (const float*)d_in[3];
    const float* b1 = (const float*)d_in[4];
    const float* v1 = (const float*)d_in[5];
    const float* W2 = (const float*)d_in[6];
    const float* b2 = (const float*)d_in[7];
    float* out = (float*)d_out;

    setup_kernel<<<1024, 256>>>(t, W1, b1, v1, W2);
    ode_kernel<<<B_ / BM, 256>>>(y, b2, out);
}